// round 8
// baseline (speedup 1.0000x reference)
#include <cuda_runtime.h>
#include <cuda_pipeline_primitives.h>

// Shapes (fixed by the problem config)
#define B_   8
#define C_   64
#define T_   50
#define H_   64
#define W_   64
#define HO_  32
#define WO_  32
#define HW_  (H_ * W_)     // 4096 floats per (b,c,t) plane
#define OHW_ (HO_ * WO_)   // 1024
#define N_OUT ((long long)B_ * C_ * T_ * HO_ * WO_)  // 26,214,400

// Block covers ONE window-row (2 h-rows) of one (b,c) plane across all T.
// Region = 2 x 64 x 50 floats = 25.6KB smem -> 8 blocks/SM.
#define REG_FLOATS (2 * 64 * T_)          // 6400
#define REG_F4     (REG_FLOATS / 4)       // 1600 float4s
#define SMEM_BYTES (REG_FLOATS * 4)       // 25600
#define NWIN 32                           // windows per block
#define NTHREADS 128

__global__ __launch_bounds__(NTHREADS, 8)
void spike_pool_smem(const float* __restrict__ x, float* __restrict__ out,
                     long long total_out) {
    const int bc = blockIdx.x >> 5;   // (b*64 + c)
    const int r  = blockIdx.x & 31;   // which window-row of the 32
    const int tid = threadIdx.x;

    extern __shared__ float sh[];     // [t][h_local(2)][w(64)] linear, 128/t
    __shared__ int sidx[NWIN];        // winning local flat index per window

    // ---- Phase 0: stream region gmem -> smem via cp.async (LDGSTS.128) ----
    // Region per t is 128 contiguous floats (32 float4) at plane offset r*128.
    const float4* gp = (const float4*)(x + (size_t)bc * (T_ * HW_) + (size_t)r * 128);
    float4* shp = (float4*)sh;
    #pragma unroll
    for (int j = 0; j < 13; ++j) {
        const int l = j * NTHREADS + tid;   // float4 index over (t, within)
        if (l < REG_F4) {
            const int t = l >> 5;           // 32 float4 per region-plane
            const int w = l & 31;
            __pipeline_memcpy_async(&shp[l], &gp[(size_t)t * (HW_ / 4) + w],
                                    sizeof(float4));
        }
    }
    __pipeline_commit();

    // Zero the out tail (loss scalar / padding) while loads are in flight.
    if (blockIdx.x == 0 && tid == 0) {
        for (long long i = N_OUT; i < total_out; ++i) out[i] = 0.0f;
    }

    __pipeline_wait_prior(0);
    __syncthreads();

    // ---- Phase 1: one thread per (window, pixel). Each pixel's cumsum-then-
    //      sum recurrence is an independent chain with FP order identical to
    //      the rel_err==0 kernels. Combine 4 pixels via shfl, first-max rule.
    {
        const int w = tid >> 2;           // window 0..31
        const int p = tid & 3;            // pixel (kh*2+kw) 0..3
        const int off = 2 * w + (p >> 1) * 64 + (p & 1);

        float a = 0.f, s = 0.f;
        #pragma unroll
        for (int t = 0; t < T_; ++t) {    // full unroll: LDS hoisted ahead of
            a += sh[t * 128 + off];       // the serial 4-cyc FADD chain
            s += a;
        }

        const unsigned full = 0xFFFFFFFFu;
        const int base = (tid & 31) & ~3;     // lane of pixel 0 in this group
        const float s0 = __shfl_sync(full, s, base + 0);
        const float s1 = __shfl_sync(full, s, base + 1);
        const float s2 = __shfl_sync(full, s, base + 2);
        const float s3 = __shfl_sync(full, s, base + 3);

        int   k    = 0;
        float best = s0;
        if (s1 > best) { best = s1; k = 1; }
        if (s2 > best) { best = s2; k = 2; }
        if (s3 > best) { best = s3; k = 3; }
        if (p == 0) sidx[w] = 2 * w + (k >> 1) * 64 + (k & 1);
    }
    __syncthreads();

    // ---- Phase 2: gather winners, write float4 (STG.128), coalesced ----
    // Thread (g, wq): t-group g in {0..15}, float4-chunk wq in {0..7}.
    // Each chunk covers windows 4*wq .. 4*wq+3.
    {
        const int g  = tid >> 3;      // 0..15
        const int wq = tid & 7;       // 0..7
        const int i0 = sidx[4 * wq + 0];
        const int i1 = sidx[4 * wq + 1];
        const int i2 = sidx[4 * wq + 2];
        const int i3 = sidx[4 * wq + 3];
        float4* ob = (float4*)(out + (size_t)bc * (T_ * OHW_) + r * NWIN) + wq;
        #pragma unroll
        for (int t = g; t < T_; t += 16) {
            const float* b = sh + t * 128;
            float4 v;
            v.x = b[i0]; v.y = b[i1]; v.z = b[i2]; v.w = b[i3];
            ob[(size_t)t * (OHW_ / 4)] = v;
        }
    }
}

extern "C" void kernel_launch(void* const* d_in, const int* in_sizes, int n_in,
                              void* d_out, int out_size) {
    const float* x = (const float*)d_in[0];
    float* out = (float*)d_out;

    cudaFuncSetAttribute(spike_pool_smem,
                         cudaFuncAttributeMaxDynamicSharedMemorySize, SMEM_BYTES);

    spike_pool_smem<<<B_ * C_ * 32, NTHREADS, SMEM_BYTES>>>(
        x, out, (long long)out_size);
}

// round 9
// speedup vs baseline: 1.0049x; 1.0049x over previous
#include <cuda_runtime.h>
#include <cuda_pipeline_primitives.h>

// Shapes (fixed by the problem config)
#define B_   8
#define C_   64
#define T_   50
#define H_   64
#define W_   64
#define HO_  32
#define WO_  32
#define HW_  (H_ * W_)     // 4096 floats per (b,c,t) plane
#define OHW_ (HO_ * WO_)   // 1024
#define N_OUT ((long long)B_ * C_ * T_ * HO_ * WO_)  // 26,214,400

// Block covers ONE window-row (2 h-rows) of one (b,c) plane across all T.
// Region = 2 x 64 x 50 floats = 25.6KB smem -> 8 blocks/SM.
#define REG_FLOATS (2 * 64 * T_)          // 6400
#define REG_F4     (REG_FLOATS / 4)       // 1600 float4s
#define SMEM_BYTES (REG_FLOATS * 4)       // 25600
#define NWIN 32                           // windows per block
#define NTHREADS 128

__global__ __launch_bounds__(NTHREADS, 8)
void spike_pool_smem(const float* __restrict__ x, float* __restrict__ out,
                     long long total_out) {
    const int bc = blockIdx.x >> 5;   // (b*64 + c)
    const int r  = blockIdx.x & 31;   // which window-row of the 32
    const int tid = threadIdx.x;

    extern __shared__ float sh[];     // [t][h_local(2)][w(64)] linear, 128/t
    __shared__ int sidx[NWIN];        // winning local flat index per window

    // ---- Phase 0: stream region gmem -> smem via cp.async (LDGSTS.128) ----
    // Region per t is 128 contiguous floats (32 float4) at plane offset r*128.
    const float4* gp = (const float4*)(x + (size_t)bc * (T_ * HW_) + (size_t)r * 128);
    float4* shp = (float4*)sh;
    #pragma unroll
    for (int j = 0; j < 13; ++j) {
        const int l = j * NTHREADS + tid;   // float4 index over (t, within)
        if (l < REG_F4) {
            const int t = l >> 5;           // 32 float4 per region-plane
            const int w = l & 31;
            __pipeline_memcpy_async(&shp[l], &gp[(size_t)t * (HW_ / 4) + w],
                                    sizeof(float4));
        }
    }
    __pipeline_commit();

    // Zero the out tail (loss scalar / padding) while loads are in flight.
    if (blockIdx.x == 0 && tid == 0) {
        for (long long i = N_OUT; i < total_out; ++i) out[i] = 0.0f;
    }

    __pipeline_wait_prior(0);
    __syncthreads();

    // ---- Phase 1: one thread per (window, pixel). Each pixel's cumsum-then-
    //      sum recurrence is an independent chain with FP order identical to
    //      the rel_err==0 kernels. Combine 4 pixels via shfl, first-max rule.
    {
        const int w = tid >> 2;           // window 0..31
        const int p = tid & 3;            // pixel (kh*2+kw) 0..3
        const int off = 2 * w + (p >> 1) * 64 + (p & 1);

        float a = 0.f, s = 0.f;
        #pragma unroll 10
        for (int t = 0; t < T_; ++t) {
            a += sh[t * 128 + off];
            s += a;
        }

        const unsigned full = 0xFFFFFFFFu;
        const int base = (tid & 31) & ~3;     // lane of pixel 0 in this group
        const float s0 = __shfl_sync(full, s, base + 0);
        const float s1 = __shfl_sync(full, s, base + 1);
        const float s2 = __shfl_sync(full, s, base + 2);
        const float s3 = __shfl_sync(full, s, base + 3);

        int   k    = 0;
        float best = s0;
        if (s1 > best) { best = s1; k = 1; }
        if (s2 > best) { best = s2; k = 2; }
        if (s3 > best) { best = s3; k = 3; }
        if (p == 0) sidx[w] = 2 * w + (k >> 1) * 64 + (k & 1);
    }
    __syncthreads();

    // ---- Phase 2: gather winner from smem for every t. One window per
    //      thread (R7 structure, 128B/warp coalesced), streaming stores so
    //      the write-once output evicts first from L2 and doesn't contend
    //      with the inbound read stream.
    const int g  = tid >> 5;      // t-group 0..3
    const int wl = tid & 31;      // window within block
    const int idx = sidx[wl];
    float* ob = out + (size_t)bc * (T_ * OHW_) + r * NWIN + wl;
    #pragma unroll
    for (int t = g; t < T_; t += 4) {
        __stcs(&ob[(size_t)t * OHW_], sh[t * 128 + idx]);
    }
}

extern "C" void kernel_launch(void* const* d_in, const int* in_sizes, int n_in,
                              void* d_out, int out_size) {
    const float* x = (const float*)d_in[0];
    float* out = (float*)d_out;

    cudaFuncSetAttribute(spike_pool_smem,
                         cudaFuncAttributeMaxDynamicSharedMemorySize, SMEM_BYTES);

    spike_pool_smem<<<B_ * C_ * 32, NTHREADS, SMEM_BYTES>>>(
        x, out, (long long)out_size);
}

// round 12
// speedup vs baseline: 1.0066x; 1.0016x over previous
#include <cuda_runtime.h>
#include <cuda_pipeline_primitives.h>

// Shapes (fixed by the problem config)
#define B_   8
#define C_   64
#define T_   50
#define H_   64
#define W_   64
#define HO_  32
#define WO_  32
#define HW_  (H_ * W_)     // 4096 floats per (b,c,t) plane
#define OHW_ (HO_ * WO_)   // 1024
#define N_OUT ((long long)B_ * C_ * T_ * HO_ * WO_)  // 26,214,400

// Block covers ONE window-row (2 h-rows) of one (b,c) plane across all T.
// Region = 2 x 64 x 50 floats = 25.6KB smem -> 8 blocks/SM.
#define REG_FLOATS (2 * 64 * T_)          // 6400
#define REG_F4     (REG_FLOATS / 4)       // 1600 float4s
#define HALF_F4    (REG_F4 / 2)           // 800 float4s  (t < 25)
#define SMEM_BYTES (REG_FLOATS * 4)       // 25600
#define NWIN 32                           // windows per block
#define NTHREADS 128

__global__ __launch_bounds__(NTHREADS, 8)
void spike_pool_smem(const float* __restrict__ x, float* __restrict__ out,
                     long long total_out) {
    const int bc = blockIdx.x >> 5;   // (b*64 + c)
    const int r  = blockIdx.x & 31;   // which window-row of the 32
    const int tid = threadIdx.x;

    extern __shared__ float sh[];     // [t][h_local(2)][w(64)] linear, 128/t
    __shared__ int sidx[NWIN];        // winning local flat index per window

    // ---- Phase 0: cp.async stage-in, split into two commit groups so the
    //      first half of the recurrence overlaps the second half's loads ----
    const float4* gp = (const float4*)(x + (size_t)bc * (T_ * HW_) + (size_t)r * 128);
    float4* shp = (float4*)sh;

    // Group A: t < 25  (l in [0, 800))
    #pragma unroll
    for (int j = 0; j < 7; ++j) {
        const int l = j * NTHREADS + tid;
        if (l < HALF_F4) {
            const int t = l >> 5;           // 32 float4 per region-plane
            const int w = l & 31;
            __pipeline_memcpy_async(&shp[l], &gp[(size_t)t * (HW_ / 4) + w],
                                    sizeof(float4));
        }
    }
    __pipeline_commit();

    // Group B: t >= 25 (l in [800, 1600))
    #pragma unroll
    for (int j = 0; j < 7; ++j) {
        const int l = HALF_F4 + j * NTHREADS + tid;
        if (l < REG_F4) {
            const int t = l >> 5;
            const int w = l & 31;
            __pipeline_memcpy_async(&shp[l], &gp[(size_t)t * (HW_ / 4) + w],
                                    sizeof(float4));
        }
    }
    __pipeline_commit();

    // Zero the out tail (loss scalar / padding) while loads are in flight.
    if (blockIdx.x == 0 && tid == 0) {
        for (long long i = N_OUT; i < total_out; ++i) out[i] = 0.0f;
    }

    // ---- Phase 1: one thread per (window, pixel). Each pixel's cumsum-then-
    //      sum recurrence is an independent chain with FP order identical to
    //      the rel_err==0 kernels (same add sequence, split at t=25). ----
    const int w = tid >> 2;           // window 0..31
    const int p = tid & 3;            // pixel (kh*2+kw) 0..3
    const int off = 2 * w + (p >> 1) * 64 + (p & 1);

    float a = 0.f, s = 0.f;

    __pipeline_wait_prior(1);         // group A resident
    __syncthreads();
    #pragma uroll 5
    #pragma unroll 5
    for (int t = 0; t < 25; ++t) {
        a += sh[t * 128 + off];
        s += a;
    }

    __pipeline_wait_prior(0);         // group B resident
    __syncthreads();
    #pragma unroll 5
    for (int t = 25; t < T_; ++t) {
        a += sh[t * 128 + off];
        s += a;
    }

    {
        const unsigned full = 0xFFFFFFFFu;
        const int base = (tid & 31) & ~3;     // lane of pixel 0 in this group
        const float s0 = __shfl_sync(full, s, base + 0);
        const float s1 = __shfl_sync(full, s, base + 1);
        const float s2 = __shfl_sync(full, s, base + 2);
        const float s3 = __shfl_sync(full, s, base + 3);

        int   k    = 0;
        float best = s0;
        if (s1 > best) { best = s1; k = 1; }
        if (s2 > best) { best = s2; k = 2; }
        if (s3 > best) { best = s3; k = 3; }
        if (p == 0) sidx[w] = 2 * w + (k >> 1) * 64 + (k & 1);
    }
    __syncthreads();

    // ---- Phase 2: gather winner from smem for every t. One window per
    //      thread, 128B/warp coalesced, streaming stores (write-once out). ----
    const int g  = tid >> 5;      // t-group 0..3
    const int wl = tid & 31;      // window within block
    const int idx = sidx[wl];
    float* ob = out + (size_t)bc * (T_ * OHW_) + r * NWIN + wl;
    #pragma unroll
    for (int t = g; t < T_; t += 4) {
        __stcs(&ob[(size_t)t * OHW_], sh[t * 128 + idx]);
    }
}

extern "C" void kernel_launch(void* const* d_in, const int* in_sizes, int n_in,
                              void* d_out, int out_size) {
    const float* x = (const float*)d_in[0];
    float* out = (float*)d_out;

    cudaFuncSetAttribute(spike_pool_smem,
                         cudaFuncAttributeMaxDynamicSharedMemorySize, SMEM_BYTES);

    spike_pool_smem<<<B_ * C_ * 32, NTHREADS, SMEM_BYTES>>>(
        x, out, (long long)out_size);
}